// round 11
// baseline (speedup 1.0000x reference)
#include <cuda_runtime.h>
#include <cstdint>

// ---------------- problem constants ----------------
#define B_    8
#define HW_   4096
#define HDIM_ 64
#define C_    1024
#define M_    32
#define P_    512

// ---------------- GEMM tiling ----------------
#define CTILE   256                 // channels per CTA
#define NBLKS   (C_ / CTILE)        // 4
#define KSPLIT  9                   // K split across grid.z (288 CTAs: balanced on 148 SMs)
#define KC      16                  // k (pixels) per chunk
#define KCHTOT  (HW_ / KC)          // 256 k-chunks per (nblk,b) column
#define NSTAGE  4
#define NCTAS   (NBLKS * B_ * KSPLIT)   // 288
#define NHIST   (B_ * M_)               // 256 histograms (CTAs with ksp<8)

// smem strides (words) — conflict-free fragment LDS, 16B-aligned rows
#define FSW 264                     // F row stride: 256 ch + 8 pad  (264%32=8)
#define WSW 36                      // W row stride: 16 k + 20 pad   (36%32=4)
#define FROWB (FSW * 4)             // 1056
#define WROWB (WSW * 4)             // 144
#define FBYTES (KC * FROWB)         // 16896
#define WBYTES (M_ * WROWB)         // 4608
#define STAGE_BYTES (FBYTES + WBYTES)       // 21504
#define SMEM_TOTAL (NSTAGE * STAGE_BYTES)   // 86016

// epilogue staging tile: [32 m][260 words]
#define ESW 260

// Scratch: tf32(RNA)-rounded weights; device-wide barrier (self-resetting)
__device__ float g_W[(size_t)B_ * M_ * HW_];
__device__ unsigned int g_bar;
__device__ unsigned int g_bar2;

// ---------------- helpers ----------------
__device__ __forceinline__ uint32_t smem_u32(const void* p) {
    uint32_t a;
    asm("{ .reg .u64 t; cvta.to.shared.u64 t, %1; cvt.u32.u64 %0, t; }" : "=r"(a) : "l"(p));
    return a;
}
__device__ __forceinline__ void cp_async16(uint32_t dst, const void* src) {
    asm volatile("cp.async.cg.shared.global [%0], [%1], 16;" :: "r"(dst), "l"(src));
}
#define CP_COMMIT() asm volatile("cp.async.commit_group;" ::: "memory")
#define CP_WAIT2()  asm volatile("cp.async.wait_group 2;" ::: "memory")

__device__ __forceinline__ uint32_t to_tf32(float x) {
    uint32_t r;
    asm("cvt.rna.tf32.f32 %0, %1;" : "=r"(r) : "f"(x));
    return r;
}
__device__ __forceinline__ void red_add_v4(float* gptr, float4 v) {
    asm volatile("red.global.add.v4.f32 [%0], {%1, %2, %3, %4};"
                 :: "l"(gptr), "f"(v.x), "f"(v.y), "f"(v.z), "f"(v.w) : "memory");
}

// D[16ch x 8m] += A[16ch x 8k] * B[8k x 8m]   (tf32, fp32 accum)
__device__ __forceinline__ void mma_tf32(float* d,
                                         uint32_t a0, uint32_t a1, uint32_t a2, uint32_t a3,
                                         uint32_t b0, uint32_t b1) {
    asm volatile(
        "mma.sync.aligned.m16n8k8.row.col.f32.tf32.tf32.f32 "
        "{%0,%1,%2,%3}, {%4,%5,%6,%7}, {%8,%9}, {%0,%1,%2,%3};"
        : "+f"(d[0]), "+f"(d[1]), "+f"(d[2]), "+f"(d[3])
        : "r"(a0), "r"(a1), "r"(a2), "r"(a3), "r"(b0), "r"(b1));
}

// ---------------------------------------------------------------------------
// Single fused kernel:
//   phase A: one (b,m) weight histogram per CTA (ksp<8) + zero its out slice
//   device-wide barrier (single wave: 288 CTAs, 2/SM x 148 = 296 slots)
//   phase B: tf32 HMMA GEMM over uneven K-split, epilogue = red.global.add.v4
// ---------------------------------------------------------------------------
__global__ void __launch_bounds__(256, 2) fused_mma(
    const float* __restrict__ coords,   // [B, M, P, 2]
    const float* __restrict__ F,        // [B, HW, C]
    float* __restrict__ out)            // [B, M, 1, C]
{
    extern __shared__ char smem[];
    const uint32_t sbase = smem_u32(smem);

    const int tid  = threadIdx.x;
    const int lane = tid & 31;
    const int wid  = tid >> 5;          // 0..7
    const int nblk = blockIdx.x;        // 0..3
    const int b    = blockIdx.y;        // 0..7
    const int ksp  = blockIdx.z;        // 0..8
    const int c0   = nblk * CTILE;

    // Uneven K-range: 256 chunks -> 29,29,29,29,28,28,28,28,28
    const int cstart = ksp * 28 + min(ksp, 4);
    const int cnt    = 28 + (ksp < 4 ? 1 : 0);

    const float* Fb = F + (size_t)b * HW_ * C_ + c0;
    const float* Wb = g_W + (size_t)b * M_ * HW_;

    // F tile loader: [16k x 256ch], local chunk index i (stage = i&3)
    auto load_F = [&](int i) {
        const int s  = i & (NSTAGE - 1);
        const int k0 = (cstart + i) * KC;
        const uint32_t fb = sbase + s * STAGE_BYTES;
        #pragma unroll
        for (int h = 0; h < 4; h++) {
            int unit = tid + h * 256;
            int row = unit >> 6;        // local k 0..15
            int uc  = unit & 63;        // 16B unit within 256-ch row
            cp_async16(fb + (uint32_t)(row * FROWB + uc * 16),
                       Fb + (size_t)(k0 + row) * C_ + uc * 4);
        }
    };
    // W tile loader: [32m x 16k]
    auto load_W = [&](int i) {
        const int s  = i & (NSTAGE - 1);
        const int k0 = (cstart + i) * KC;
        const uint32_t wb = sbase + s * STAGE_BYTES + FBYTES;
        if (tid < 128) {
            int m  = tid >> 2;
            int kq = tid & 3;
            cp_async16(wb + (uint32_t)(m * WROWB + kq * 16),
                       Wb + (size_t)m * HW_ + k0 + kq * 4);
        }
    };

    // ---- F prefetch first (independent of weights) ----
    load_F(0); CP_COMMIT();
    load_F(1); CP_COMMIT();
    load_F(2); CP_COMMIT();

    // ---- Phase A: histogram + out-slice zero for CTAs with ksp < 8 ----
    if (ksp < 8) {
        const int flat = nblk + NBLKS * (b + B_ * ksp);     // bijection 0..255

        // zero output slice (one float4 per thread)
        float4* oz = reinterpret_cast<float4*>(out + (size_t)flat * 1024);
        oz[tid] = make_float4(0.f, 0.f, 0.f, 0.f);

        float* hist = reinterpret_cast<float*>(smem + 3 * STAGE_BYTES);
        #pragma unroll 4
        for (int i = tid; i < HW_; i += 256) hist[i] = 0.0f;
        __syncthreads();

        const float* cp = coords + (size_t)flat * P_ * 2;
        const float invP = 1.0f / (float)P_;
        const float s = (float)(HDIM_ - 1);

        for (int p = tid; p < P_; p += 256) {
            float yn = cp[p * 2 + 0];
            float xn = cp[p * 2 + 1];
            float y = yn * s;
            float x = xn * s;
            float x0f = floorf(x), y0f = floorf(y);
            float wx = x - x0f, wy = y - y0f;
            int ix0 = min(max((int)x0f, 0), HDIM_ - 1);
            int ix1 = min(ix0 + 1, HDIM_ - 1);
            int iy0 = min(max((int)y0f, 0), HDIM_ - 1);
            int iy1 = min(iy0 + 1, HDIM_ - 1);
            atomicAdd(&hist[iy0 * HDIM_ + ix0], (1.0f - wx) * (1.0f - wy) * invP);
            atomicAdd(&hist[iy0 * HDIM_ + ix1], wx * (1.0f - wy) * invP);
            atomicAdd(&hist[iy1 * HDIM_ + ix0], (1.0f - wx) * wy * invP);
            atomicAdd(&hist[iy1 * HDIM_ + ix1], wx * wy * invP);
        }
        __syncthreads();

        float* wout = g_W + (size_t)flat * HW_;
        #pragma unroll 4
        for (int i = tid; i < HW_; i += 256)
            wout[i] = __uint_as_float(to_tf32(hist[i]));
    }

    // ---- Device-wide barrier (single wave: all 288 CTAs co-resident) ----
    __threadfence();
    __syncthreads();
    if (tid == 0) {
        atomicAdd(&g_bar, 1u);
        while (*((volatile unsigned int*)&g_bar) < NCTAS) {}
    }
    __syncthreads();
    __threadfence();    // acquire all g_W writes + out zeroing

    // ---- W prologue (group schedule F0 F1 F2 W0 W1 W2, validated R7/R9/R10)
    load_W(0); CP_COMMIT();
    load_W(1); CP_COMMIT();
    load_W(2); CP_COMMIT();

    const int r = lane >> 2;            // 0..7
    const int c = lane & 3;             // 0..3
    const int chw = wid * 32;           // warp channel base within tile

    float d[2][4][4];
    #pragma unroll
    for (int t = 0; t < 2; t++)
        #pragma unroll
        for (int j = 0; j < 4; j++)
            #pragma unroll
            for (int e = 0; e < 4; e++) d[t][j][e] = 0.f;

    for (int i = 0; i < cnt; i++) {
        CP_WAIT2();                 // chunk i resident (F(i) and W(i))
        __syncthreads();

        const float* fptr = reinterpret_cast<const float*>(smem + (i & (NSTAGE - 1)) * STAGE_BYTES);
        const float* wptr = fptr + KC * FSW;

        #pragma unroll
        for (int ks = 0; ks < KC / 8; ks++) {
            const int kr = ks * 8;
            // A = F fragments: 2 sets of 16 ch
            uint32_t a[2][4];
            #pragma unroll
            for (int t = 0; t < 2; t++) {
                const int chb = chw + t * 16;
                a[t][0] = to_tf32(fptr[(kr + c) * FSW + chb + r]);
                a[t][1] = to_tf32(fptr[(kr + c) * FSW + chb + r + 8]);
                a[t][2] = to_tf32(fptr[(kr + c + 4) * FSW + chb + r]);
                a[t][3] = to_tf32(fptr[(kr + c + 4) * FSW + chb + r + 8]);
            }
            // B = W fragments: 4 sets of 8 m (already tf32)
            uint32_t bf[4][2];
            #pragma unroll
            for (int j = 0; j < 4; j++) {
                bf[j][0] = __float_as_uint(wptr[(j * 8 + r) * WSW + kr + c]);
                bf[j][1] = __float_as_uint(wptr[(j * 8 + r) * WSW + kr + c + 4]);
            }
            #pragma unroll
            for (int t = 0; t < 2; t++)
                #pragma unroll
                for (int j = 0; j < 4; j++)
                    mma_tf32(d[t][j], a[t][0], a[t][1], a[t][2], a[t][3],
                             bf[j][0], bf[j][1]);
        }

        if (i + 3 < cnt) { load_F(i + 3); load_W(i + 3); }
        CP_COMMIT();                // one group per iteration (may be empty)
    }

    // ---- epilogue: stage D[32m x 256ch] in smem, then coalesced v4 L2-reductions
    __syncthreads();                // all compute done; reuse stage 0/1 smem
    {
        float* etile = reinterpret_cast<float*>(smem);      // [32][ESW]
        // D map per mma: thread (r,c) holds (ch, m=2c), (ch, 2c+1), (ch+8, 2c), (ch+8, 2c+1)
        #pragma unroll
        for (int t = 0; t < 2; t++) {
            const int ch = chw + t * 16 + r;
            #pragma unroll
            for (int j = 0; j < 4; j++) {
                int mA = j * 8 + 2 * c, mB = mA + 1;
                etile[mA * ESW + ch]     = d[t][j][0];
                etile[mB * ESW + ch]     = d[t][j][1];
                etile[mA * ESW + ch + 8] = d[t][j][2];
                etile[mB * ESW + ch + 8] = d[t][j][3];
            }
        }
        __syncthreads();

        float* ob = out + (size_t)b * M_ * C_ + c0;
        #pragma unroll
        for (int h = 0; h < 8; h++) {
            int idx = tid + h * 256;        // 0..2047
            int m = idx >> 6;               // 0..31
            int q = idx & 63;               // float4 slot within 256 ch
            const float4 v = *reinterpret_cast<const float4*>(etile + m * ESW + q * 4);
            red_add_v4(ob + (size_t)m * C_ + q * 4, v);
        }
    }

    // ---- barrier self-reset (safe: all CTAs are past the first barrier) ----
    __syncthreads();
    if (tid == 0) {
        unsigned int old = atomicAdd(&g_bar2, 1u);
        if (old == NCTAS - 1) {
            g_bar = 0;
            g_bar2 = 0;
            __threadfence();
        }
    }
}

// ---------------------------------------------------------------------------
extern "C" void kernel_launch(void* const* d_in, const int* in_sizes, int n_in,
                              void* d_out, int out_size)
{
    const float* feature = (const float*)d_in[0];
    const float* coords  = (const float*)d_in[1];
    if (n_in >= 2 && in_sizes[0] == B_ * M_ * P_ * 2) {
        feature = (const float*)d_in[1];
        coords  = (const float*)d_in[0];
    }

    cudaFuncSetAttribute(fused_mma, cudaFuncAttributeMaxDynamicSharedMemorySize, SMEM_TOTAL);

    dim3 g2(NBLKS, B_, KSPLIT);
    fused_mma<<<g2, 256, SMEM_TOTAL>>>(coords, feature, (float*)d_out);
}